// round 5
// baseline (speedup 1.0000x reference)
#include <cuda_runtime.h>
#include <cuda_bf16.h>
#include <cstdint>

// ---------------- problem constants ----------------
#define NX       51380224            // 32*128*112*112
#define NW       147456              // 128*128*3*3
#define HW       12544               // 112*112
#define WDIM     112
#define CIN      128
#define COUT     128
#define KK       9

#define GROUP    36
#define EPB      9216                // elems per quant block (256 groups)

// scratch (static device globals)
__device__ __nv_bfloat16 g_xn[NX];             // quantized bf16, NCHW
__device__ __nv_bfloat16 g_xt[NX];             // quantized bf16, NHWC
__device__ __nv_bfloat16 g_w[KK * COUT * CIN]; // quantized bf16, [k][co][ci]

// ---------------- helpers ----------------
__device__ __forceinline__ uint32_t smem_u32(const void* p) {
    uint32_t a;
    asm("{ .reg .u64 t; cvta.to.shared.u64 t, %1; cvt.u32.u64 %0, t; }" : "=r"(a) : "l"(p));
    return a;
}

__device__ __forceinline__ void cp_async16(uint32_t dst, const void* src, uint32_t src_bytes) {
    asm volatile("cp.async.ca.shared.global [%0], [%1], 16, %2;"
                 :: "r"(dst), "l"(src), "r"(src_bytes) : "memory");
}
#define CP_COMMIT()  asm volatile("cp.async.commit_group;" ::: "memory")
#define CP_WAIT(n)   asm volatile("cp.async.wait_group %0;" :: "n"(n) : "memory")

__device__ __forceinline__ void ldmatrix_x4(uint32_t* r, uint32_t addr) {
    asm volatile("ldmatrix.sync.aligned.m8n8.x4.shared.b16 {%0,%1,%2,%3}, [%4];"
                 : "=r"(r[0]), "=r"(r[1]), "=r"(r[2]), "=r"(r[3]) : "r"(addr));
}

__device__ __forceinline__ void mma_bf16(float* d, const uint32_t* a, const uint32_t* b) {
    asm volatile(
        "mma.sync.aligned.m16n8k16.row.col.f32.bf16.bf16.f32 "
        "{%0,%1,%2,%3}, {%4,%5,%6,%7}, {%8,%9}, {%0,%1,%2,%3};"
        : "+f"(d[0]), "+f"(d[1]), "+f"(d[2]), "+f"(d[3])
        : "r"(a[0]), "r"(a[1]), "r"(a[2]), "r"(a[3]), "r"(b[0]), "r"(b[1]));
}

// ---------------- quantization ----------------
__device__ __forceinline__ float bfp_q(float v, float inv_step, float step) {
    float q = rintf(v * inv_step);            // exact (power-of-2 mul), half-to-even
    q = fminf(fmaxf(q, -128.0f), 127.0f);
    return q * step;                          // exact
}

// quant_x: block = 9216 contiguous elems = 256 groups; writes bf16 NCHW
__global__ void __launch_bounds__(256) quant_x_kernel(const float* __restrict__ x) {
    __shared__ float sm[EPB];
    const long base = (long)blockIdx.x * EPB;
    const int tid = threadIdx.x;

    const float4* xv = (const float4*)(x + base);
    float4* smv = (float4*)sm;
    if (base + EPB <= NX) {
#pragma unroll
        for (int i = 0; i < 9; i++) smv[tid + i * 256] = xv[tid + i * 256];
    } else {
        for (int i = 0; i < 9; i++) {
            int e4 = tid + i * 256;
            long e = base + (long)e4 * 4;
            float4 v = make_float4(0.f, 0.f, 0.f, 0.f);
            if (e + 3 < NX) v = xv[e4];
            else {
                float* vp = (float*)&v;
                for (int j = 0; j < 4; j++) if (e + j < NX) vp[j] = x[e + j];
            }
            smv[e4] = v;
        }
    }
    __syncthreads();

    const float* g = sm + tid * GROUP;
    float mx = 0.0f;
#pragma unroll
    for (int i = 0; i < GROUP; i++) mx = fmaxf(mx, fabsf(g[i]));

    __nv_bfloat16* ob = (__nv_bfloat16*)((char*)sm + (size_t)tid * (GROUP * 4));
    if (mx > 0.0f) {
        int e = ilogbf(mx);
        float st  = exp2f((float)(e - 7));
        float inv = exp2f((float)(7 - e));
#pragma unroll
        for (int i = 0; i < GROUP; i++) ob[i] = __float2bfloat16(bfp_q(g[i], inv, st));
    } else {
#pragma unroll
        for (int i = 0; i < GROUP; i++) ob[i] = __float2bfloat16(0.0f);
    }
    __syncthreads();

    for (int j = 0; j < 9; j++) {
        int m = tid + j * 256;
        int t2 = m / 9, sub = m % 9;
        uint2 v = *(const uint2*)((char*)sm + (size_t)t2 * 144 + (size_t)sub * 8);
        long e0 = base + (long)m * 4;
        if (e0 + 3 < NX) {
            *(uint2*)(g_xn + e0) = v;
        } else {
            const __nv_bfloat16* vp = (const __nv_bfloat16*)&v;
            for (int q = 0; q < 4; q++) if (e0 + q < NX) g_xn[e0 + q] = vp[q];
        }
    }
}

// quant_w: 4096 groups of 36 (exact); writes bf16 transposed [k][co][ci]
__global__ void quant_w_kernel(const float* __restrict__ w) {
    int grp = blockIdx.x * blockDim.x + threadIdx.x;
    if (grp >= NW / GROUP) return;
    const float* p = w + grp * GROUP;

    float mx = 0.0f;
#pragma unroll
    for (int i = 0; i < GROUP; i++) mx = fmaxf(mx, fabsf(p[i]));

    float st = 0.0f, inv = 0.0f;
    bool nz = (mx > 0.0f);
    if (nz) {
        int e = ilogbf(mx);
        st  = exp2f((float)(e - 7));
        inv = exp2f((float)(7 - e));
    }
#pragma unroll
    for (int i = 0; i < GROUP; i++) {
        int f  = grp * GROUP + i;
        int co = f / (CIN * KK);
        int r  = f % (CIN * KK);
        int ci = r / KK;
        int k  = r % KK;
        float q = nz ? bfp_q(p[i], inv, st) : 0.0f;
        g_w[k * (COUT * CIN) + co * CIN + ci] = __float2bfloat16(q);
    }
}

// ---------------- NCHW -> NHWC bf16 transpose ----------------
__global__ void __launch_bounds__(256) transpose_x_kernel() {
    __shared__ __nv_bfloat16 sm[128 * 72];
    const int tid = threadIdx.x;
    const int blk = blockIdx.x;
    const int b = blk / 196;
    const int p0 = (blk % 196) * 64;

#pragma unroll
    for (int i = 0; i < 4; i++) {
        int u = tid + i * 256;
        int ci = u >> 3, seg = u & 7;
        uint4 v = *(const uint4*)(g_xn + ((long)(b * CIN + ci) * HW + p0 + seg * 8));
        int col = (seg * 8) ^ (((ci >> 3) & 7) << 3);
        *(uint4*)(&sm[ci * 72 + col]) = v;
    }
    __syncthreads();

#pragma unroll
    for (int i = 0; i < 4; i++) {
        int u = tid + i * 256;
        int px = u >> 4, s2 = u & 15;
        __nv_bfloat16 tmp[8];
        int col = px ^ ((s2 & 7) << 3);
#pragma unroll
        for (int j = 0; j < 8; j++) tmp[j] = sm[(s2 * 8 + j) * 72 + col];
        *(uint4*)(g_xt + ((long)(b * HW + p0 + px) * CIN + s2 * 8)) = *(const uint4*)tmp;
    }
}

// ---------------- HMMA implicit-GEMM conv ----------------
// CTA: 128 Cout x 128 px, 128 threads = 4 warps (2 M x 2 N), warp tile 64x64.
// K = 9 taps x 128 ci = 36 chunks of 32; 4-stage cp.async ring, 1 sync/chunk.
// smem per stage: A[128][32] + B[128][32] bf16, pitch 80B (conflict-free ldmatrix).
#define PITCH  80
#define STG_SZ (128 * PITCH)       // 10240 B per tile
#define STAGES 4

__global__ void __launch_bounds__(128, 2) conv_hmma_kernel(const float* __restrict__ bias,
                                                           float* __restrict__ out) {
    extern __shared__ __align__(16) char smem[];   // STAGES*(A+B) = 81920 B
    char* sA = smem;                    // [STAGES][STG_SZ]
    char* sB = smem + STAGES * STG_SZ;  // [STAGES][STG_SZ]

    const int tid  = threadIdx.x;
    const int lane = tid & 31, wid = tid >> 5;
    const int wm = wid >> 1, wn = wid & 1;      // warp grid 2x2
    const int b  = blockIdx.x / 98;
    const int s0 = (blockIdx.x % 98) * 128;

    // loader: thread t -> full 32-ci row t (4 x 16B)
    const int px = s0 + tid;
    const int h = px / WDIM, w = px % WDIM;
    const long xb = (long)b * HW * CIN;

    uint32_t dA[STAGES], dB[STAGES];
#pragma unroll
    for (int s = 0; s < STAGES; s++) {
        dA[s] = smem_u32(sA + s * STG_SZ + tid * PITCH);
        dB[s] = smem_u32(sB + s * STG_SZ + tid * PITCH);
    }

    float acc[4][8][4];
#pragma unroll
    for (int i = 0; i < 4; i++)
#pragma unroll
        for (int j = 0; j < 8; j++)
#pragma unroll
            for (int q = 0; q < 4; q++) acc[i][j][q] = 0.0f;

    auto issue = [&](int c, int stg) {
        int t = c >> 2, q = c & 3;               // tap, ci-quarter
        const __nv_bfloat16* wsrc = g_w + t * (COUT * CIN) + tid * CIN + q * 32;
#pragma unroll
        for (int seg = 0; seg < 4; seg++)
            cp_async16(dA[stg] + seg * 16, wsrc + seg * 8, 16u);
        int dh = t / 3 - 1, dw = t % 3 - 1;
        int hh = h + dh, ww = w + dw;
        uint32_t vb = ((unsigned)hh < WDIM && (unsigned)ww < WDIM) ? 16u : 0u;
        const __nv_bfloat16* xsrc = g_xt + xb + ((long)(hh * WDIM + ww)) * CIN + q * 32;
#pragma unroll
        for (int seg = 0; seg < 4; seg++)
            cp_async16(dB[stg] + seg * 16, xsrc + seg * 8, vb);
        CP_COMMIT();
    };

    issue(0, 0); issue(1, 1); issue(2, 2);

    const uint32_t aRow = (uint32_t)((wm * 64 + (lane & 15)) * PITCH + (lane >> 4) * 16);
    const uint32_t bRow = (uint32_t)((wn * 64 + (lane & 7) + ((lane >> 4) << 3)) * PITCH
                                     + ((lane >> 3) & 1) * 16);
    const uint32_t sA0 = smem_u32(sA), sB0 = smem_u32(sB);

    for (int c = 0; c < 36; c++) {
        CP_WAIT(2);
        __syncthreads();
        if (c + 3 < 36) issue(c + 3, (c + 3) & 3); else CP_COMMIT();

        const int stg = c & 3;
        uint32_t baseA = sA0 + stg * STG_SZ + aRow;
        uint32_t baseB = sB0 + stg * STG_SZ + bRow;
#pragma unroll
        for (int ks = 0; ks < 2; ks++) {
            uint32_t afr[4][4];
#pragma unroll
            for (int i = 0; i < 4; i++)
                ldmatrix_x4(afr[i], baseA + i * 16 * PITCH + ks * 32);
            uint32_t bfr[4][4];
#pragma unroll
            for (int jj = 0; jj < 4; jj++)
                ldmatrix_x4(bfr[jj], baseB + jj * 16 * PITCH + ks * 32);
#pragma unroll
            for (int i = 0; i < 4; i++)
#pragma unroll
                for (int j = 0; j < 8; j++)
                    mma_bf16(acc[i][j], afr[i], &bfr[j >> 1][(j & 1) * 2]);
        }
    }

    // epilogue: rows co = wm*64+i*16+{lane>>2,+8}; cols px = wn*64+j*8+(lane&3)*2
    float* ob = out + (long)b * (COUT * HW) + s0;
#pragma unroll
    for (int i = 0; i < 4; i++) {
        int r0 = wm * 64 + i * 16 + (lane >> 2);
        int r1 = r0 + 8;
        float bv0 = __ldg(&bias[r0]);
        float bv1 = __ldg(&bias[r1]);
        float* p0 = ob + (long)r0 * HW;
        float* p1 = ob + (long)r1 * HW;
#pragma unroll
        for (int j = 0; j < 8; j++) {
            int col = wn * 64 + j * 8 + (lane & 3) * 2;
            *(float2*)(p0 + col) = make_float2(acc[i][j][0] + bv0, acc[i][j][1] + bv0);
            *(float2*)(p1 + col) = make_float2(acc[i][j][2] + bv1, acc[i][j][3] + bv1);
        }
    }
}

// ---------------- launch ----------------
extern "C" void kernel_launch(void* const* d_in, const int* in_sizes, int n_in,
                              void* d_out, int out_size) {
    const float* x    = (const float*)d_in[0];
    const float* wgt  = (const float*)d_in[1];
    const float* bias = (const float*)d_in[2];
    float* out = (float*)d_out;

    cudaFuncSetAttribute(conv_hmma_kernel,
                         cudaFuncAttributeMaxDynamicSharedMemorySize, 2 * STAGES * STG_SZ);

    quant_x_kernel<<<(NX + EPB - 1) / EPB, 256>>>(x);
    quant_w_kernel<<<(NW / GROUP + 255) / 256, 256>>>(wgt);
    transpose_x_kernel<<<32 * 196, 256>>>();
    conv_hmma_kernel<<<32 * 98, 128, 2 * STAGES * STG_SZ>>>(bias, out);
}

// round 6
// speedup vs baseline: 1.3271x; 1.3271x over previous
#include <cuda_runtime.h>
#include <cuda_bf16.h>
#include <cstdint>

// ---------------- problem constants ----------------
#define NX       51380224            // 32*128*112*112
#define NW       147456              // 128*128*3*3
#define HW       12544               // 112*112
#define WDIM     112
#define CIN      128
#define COUT     128
#define KK       9

#define GROUP    36
#define EPB      9216                // elems per quant block (256 groups)

// scratch (static device globals)
__device__ __nv_bfloat16 g_xn[NX];             // quantized bf16, NCHW
__device__ __nv_bfloat16 g_xt[NX];             // quantized bf16, NHWC
__device__ __nv_bfloat16 g_w[KK * COUT * CIN]; // quantized bf16, [k][co][ci]

// ---------------- helpers ----------------
__device__ __forceinline__ uint32_t smem_u32(const void* p) {
    uint32_t a;
    asm("{ .reg .u64 t; cvta.to.shared.u64 t, %1; cvt.u32.u64 %0, t; }" : "=r"(a) : "l"(p));
    return a;
}

__device__ __forceinline__ void cp_async16(uint32_t dst, const void* src, uint32_t src_bytes) {
    asm volatile("cp.async.cg.shared.global [%0], [%1], 16, %2;"
                 :: "r"(dst), "l"(src), "r"(src_bytes) : "memory");
}
#define CP_COMMIT()  asm volatile("cp.async.commit_group;" ::: "memory")
#define CP_WAIT(n)   asm volatile("cp.async.wait_group %0;" :: "n"(n) : "memory")

__device__ __forceinline__ void ldmatrix_x4(uint32_t* r, uint32_t addr) {
    asm volatile("ldmatrix.sync.aligned.m8n8.x4.shared.b16 {%0,%1,%2,%3}, [%4];"
                 : "=r"(r[0]), "=r"(r[1]), "=r"(r[2]), "=r"(r[3]) : "r"(addr));
}

__device__ __forceinline__ void mma_bf16(float* d, const uint32_t* a, const uint32_t* b) {
    asm volatile(
        "mma.sync.aligned.m16n8k16.row.col.f32.bf16.bf16.f32 "
        "{%0,%1,%2,%3}, {%4,%5,%6,%7}, {%8,%9}, {%0,%1,%2,%3};"
        : "+f"(d[0]), "+f"(d[1]), "+f"(d[2]), "+f"(d[3])
        : "r"(a[0]), "r"(a[1]), "r"(a[2]), "r"(a[3]), "r"(b[0]), "r"(b[1]));
}

// ---------------- quantization ----------------
__device__ __forceinline__ float bfp_q(float v, float inv_step, float step) {
    float q = rintf(v * inv_step);            // exact (power-of-2 mul), half-to-even
    q = fminf(fmaxf(q, -128.0f), 127.0f);
    return q * step;                          // exact
}

// quant_x: block = 9216 contiguous elems = 256 groups; writes bf16 NCHW
__global__ void __launch_bounds__(256) quant_x_kernel(const float* __restrict__ x) {
    __shared__ float sm[EPB];
    const long base = (long)blockIdx.x * EPB;
    const int tid = threadIdx.x;

    const float4* xv = (const float4*)(x + base);
    float4* smv = (float4*)sm;
    if (base + EPB <= NX) {
#pragma unroll
        for (int i = 0; i < 9; i++) smv[tid + i * 256] = xv[tid + i * 256];
    } else {
        for (int i = 0; i < 9; i++) {
            int e4 = tid + i * 256;
            long e = base + (long)e4 * 4;
            float4 v = make_float4(0.f, 0.f, 0.f, 0.f);
            if (e + 3 < NX) v = xv[e4];
            else {
                float* vp = (float*)&v;
                for (int j = 0; j < 4; j++) if (e + j < NX) vp[j] = x[e + j];
            }
            smv[e4] = v;
        }
    }
    __syncthreads();

    const float* g = sm + tid * GROUP;
    float mx = 0.0f;
#pragma unroll
    for (int i = 0; i < GROUP; i++) mx = fmaxf(mx, fabsf(g[i]));

    __nv_bfloat16* ob = (__nv_bfloat16*)((char*)sm + (size_t)tid * (GROUP * 4));
    if (mx > 0.0f) {
        int e = ilogbf(mx);
        float st  = exp2f((float)(e - 7));
        float inv = exp2f((float)(7 - e));
#pragma unroll
        for (int i = 0; i < GROUP; i++) ob[i] = __float2bfloat16(bfp_q(g[i], inv, st));
    } else {
#pragma unroll
        for (int i = 0; i < GROUP; i++) ob[i] = __float2bfloat16(0.0f);
    }
    __syncthreads();

    for (int j = 0; j < 9; j++) {
        int m = tid + j * 256;
        int t2 = m / 9, sub = m % 9;
        uint2 v = *(const uint2*)((char*)sm + (size_t)t2 * 144 + (size_t)sub * 8);
        long e0 = base + (long)m * 4;
        if (e0 + 3 < NX) {
            *(uint2*)(g_xn + e0) = v;
        } else {
            const __nv_bfloat16* vp = (const __nv_bfloat16*)&v;
            for (int q = 0; q < 4; q++) if (e0 + q < NX) g_xn[e0 + q] = vp[q];
        }
    }
}

// quant_w: 4096 groups of 36 (exact); writes bf16 transposed [k][co][ci]
__global__ void quant_w_kernel(const float* __restrict__ w) {
    int grp = blockIdx.x * blockDim.x + threadIdx.x;
    if (grp >= NW / GROUP) return;
    const float* p = w + grp * GROUP;

    float mx = 0.0f;
#pragma unroll
    for (int i = 0; i < GROUP; i++) mx = fmaxf(mx, fabsf(p[i]));

    float st = 0.0f, inv = 0.0f;
    bool nz = (mx > 0.0f);
    if (nz) {
        int e = ilogbf(mx);
        st  = exp2f((float)(e - 7));
        inv = exp2f((float)(7 - e));
    }
#pragma unroll
    for (int i = 0; i < GROUP; i++) {
        int f  = grp * GROUP + i;
        int co = f / (CIN * KK);
        int r  = f % (CIN * KK);
        int ci = r / KK;
        int k  = r % KK;
        float q = nz ? bfp_q(p[i], inv, st) : 0.0f;
        g_w[k * (COUT * CIN) + co * CIN + ci] = __float2bfloat16(q);
    }
}

// ---------------- NCHW -> NHWC bf16 transpose ----------------
__global__ void __launch_bounds__(256) transpose_x_kernel() {
    __shared__ __nv_bfloat16 sm[128 * 72];
    const int tid = threadIdx.x;
    const int blk = blockIdx.x;
    const int b = blk / 196;
    const int p0 = (blk % 196) * 64;

#pragma unroll
    for (int i = 0; i < 4; i++) {
        int u = tid + i * 256;
        int ci = u >> 3, seg = u & 7;
        uint4 v = *(const uint4*)(g_xn + ((long)(b * CIN + ci) * HW + p0 + seg * 8));
        int col = (seg * 8) ^ (((ci >> 3) & 7) << 3);
        *(uint4*)(&sm[ci * 72 + col]) = v;
    }
    __syncthreads();

#pragma unroll
    for (int i = 0; i < 4; i++) {
        int u = tid + i * 256;
        int px = u >> 4, s2 = u & 15;
        __nv_bfloat16 tmp[8];
        int col = px ^ ((s2 & 7) << 3);
#pragma unroll
        for (int j = 0; j < 8; j++) tmp[j] = sm[(s2 * 8 + j) * 72 + col];
        *(uint4*)(g_xt + ((long)(b * HW + p0 + px) * CIN + s2 * 8)) = *(const uint4*)tmp;
    }
}

// ---------------- HMMA implicit-GEMM conv ----------------
// CTA: 128 Cout x 128 px, 256 threads = 8 warps (2 M x 4 N), warp tile 64x32.
// K = 9 taps x 128 ci = 36 chunks of 32; 4-stage cp.async ring, 1 sync/chunk.
// smem per stage: A[128][32] + B[128][32] bf16, pitch 80B (conflict-free ldmatrix).
#define PITCH  80
#define STG_SZ (2 * 128 * PITCH)     // A tile + B tile per stage = 20480 B
#define STAGES 4

__global__ void __launch_bounds__(256, 2) conv_hmma_kernel(const float* __restrict__ bias,
                                                           float* __restrict__ out) {
    extern __shared__ __align__(16) char smem[];   // STAGES*STG_SZ = 81920 B

    const int tid  = threadIdx.x;
    const int lane = tid & 31, wid = tid >> 5;
    const int wm = wid >> 2, wn = wid & 3;      // warp grid 2x4
    const int b  = blockIdx.x / 98;
    const int s0 = (blockIdx.x % 98) * 128;

    // loader: thread -> (row, 2 consecutive 16B chunks)
    const int lrow = tid >> 1;
    const int lc   = (tid & 1) * 2;
    const int px = s0 + lrow;
    const int h = px / WDIM, w = px % WDIM;
    const long xb = (long)b * HW * CIN;

    uint32_t dA[STAGES], dB[STAGES];
#pragma unroll
    for (int s = 0; s < STAGES; s++) {
        dA[s] = smem_u32(smem + s * STG_SZ + lrow * PITCH + lc * 16);
        dB[s] = dA[s] + 128 * PITCH;
    }

    float acc[4][4][4];
#pragma unroll
    for (int i = 0; i < 4; i++)
#pragma unroll
        for (int j = 0; j < 4; j++)
#pragma unroll
            for (int q = 0; q < 4; q++) acc[i][j][q] = 0.0f;

    auto issue = [&](int c, int stg) {
        int t = c >> 2, q = c & 3;               // tap, ci-quarter
        const __nv_bfloat16* wsrc = g_w + t * (COUT * CIN) + lrow * CIN + q * 32 + lc * 8;
        cp_async16(dA[stg],      wsrc,     16u);
        cp_async16(dA[stg] + 16, wsrc + 8, 16u);
        int dh = t / 3 - 1, dw = t % 3 - 1;
        int hh = h + dh, ww = w + dw;
        uint32_t vb = ((unsigned)hh < WDIM && (unsigned)ww < WDIM) ? 16u : 0u;
        const __nv_bfloat16* xsrc = g_xt + xb + ((long)(hh * WDIM + ww)) * CIN + q * 32 + lc * 8;
        cp_async16(dB[stg],      xsrc,     vb);
        cp_async16(dB[stg] + 16, xsrc + 8, vb);
        CP_COMMIT();
    };

    issue(0, 0); issue(1, 1); issue(2, 2);

    const uint32_t aRow = (uint32_t)((wm * 64 + (lane & 15)) * PITCH + (lane >> 4) * 16);
    const uint32_t bRow = (uint32_t)(128 * PITCH
                                     + (wn * 32 + (lane & 7) + ((lane >> 4) << 3)) * PITCH
                                     + ((lane >> 3) & 1) * 16);
    const uint32_t s0addr = smem_u32(smem);

    for (int c = 0; c < 36; c++) {
        CP_WAIT(2);
        __syncthreads();
        if (c + 3 < 36) issue(c + 3, (c + 3) & 3); else CP_COMMIT();

        const uint32_t stgBase = s0addr + (uint32_t)((c & 3) * STG_SZ);
        const uint32_t baseA = stgBase + aRow;
        const uint32_t baseB = stgBase + bRow;
#pragma unroll
        for (int ks = 0; ks < 2; ks++) {
            uint32_t afr[4][4];
#pragma unroll
            for (int i = 0; i < 4; i++)
                ldmatrix_x4(afr[i], baseA + i * 16 * PITCH + ks * 32);
            uint32_t bfr[2][4];
#pragma unroll
            for (int jj = 0; jj < 2; jj++)
                ldmatrix_x4(bfr[jj], baseB + jj * 16 * PITCH + ks * 32);
#pragma unroll
            for (int i = 0; i < 4; i++)
#pragma unroll
                for (int j = 0; j < 4; j++)
                    mma_bf16(acc[i][j], afr[i], &bfr[j >> 1][(j & 1) * 2]);
        }
    }

    // epilogue: rows co = wm*64+i*16+{lane>>2,+8}; cols px = wn*32+j*8+(lane&3)*2
    float* ob = out + (long)b * (COUT * HW) + s0;
#pragma unroll
    for (int i = 0; i < 4; i++) {
        int r0 = wm * 64 + i * 16 + (lane >> 2);
        int r1 = r0 + 8;
        float bv0 = __ldg(&bias[r0]);
        float bv1 = __ldg(&bias[r1]);
        float* p0 = ob + (long)r0 * HW;
        float* p1 = ob + (long)r1 * HW;
#pragma unroll
        for (int j = 0; j < 4; j++) {
            int col = wn * 32 + j * 8 + (lane & 3) * 2;
            *(float2*)(p0 + col) = make_float2(acc[i][j][0] + bv0, acc[i][j][1] + bv0);
            *(float2*)(p1 + col) = make_float2(acc[i][j][2] + bv1, acc[i][j][3] + bv1);
        }
    }
}

// ---------------- launch ----------------
extern "C" void kernel_launch(void* const* d_in, const int* in_sizes, int n_in,
                              void* d_out, int out_size) {
    const float* x    = (const float*)d_in[0];
    const float* wgt  = (const float*)d_in[1];
    const float* bias = (const float*)d_in[2];
    float* out = (float*)d_out;

    cudaFuncSetAttribute(conv_hmma_kernel,
                         cudaFuncAttributeMaxDynamicSharedMemorySize, STAGES * STG_SZ);

    quant_x_kernel<<<(NX + EPB - 1) / EPB, 256>>>(x);
    quant_w_kernel<<<(NW / GROUP + 255) / 256, 256>>>(wgt);
    transpose_x_kernel<<<32 * 196, 256>>>();
    conv_hmma_kernel<<<32 * 98, 256, STAGES * STG_SZ>>>(bias, out);
}